// round 1
// baseline (speedup 1.0000x reference)
#include <cuda_runtime.h>

// Problem constants (fixed by setup_inputs)
#define M_TOT 8192      // B*N = 4*2048
#define D_DIM 2048      // input dim
#define O_DIM 2048      // output dim
#define E_NUM 8         // experts
#define R_DIM 16        // lora rank
#define KLORA 128       // E*R
#define K_TOT 2176      // D_DIM + KLORA

// Scratch (static device globals; no runtime allocation)
__device__ float g_rw[M_TOT * E_NUM];            // router weights (sparse softmax), 256 KB
__device__ float g_Z[(size_t)M_TOT * KLORA];     // weighted lora-down activations, 4 MB
__device__ float g_WB[(size_t)O_DIM * K_TOT];    // [W | Bcat^T] concatenated, N-major K-contig, 17.8 MB

// ---------------------------------------------------------------------------
// Kernel 1: router logits + top-2 sparse softmax.
// One block (256 threads) per row. logits[e] = dot(x_row, Wr[e]).
// ---------------------------------------------------------------------------
__global__ __launch_bounds__(256) void router_kernel(
    const float* __restrict__ x, const float* __restrict__ Wr)
{
    const int row = blockIdx.x;
    const int t = threadIdx.x;
    const float4* xr = reinterpret_cast<const float4*>(x + (size_t)row * D_DIM);

    float acc[E_NUM];
#pragma unroll
    for (int e = 0; e < E_NUM; e++) acc[e] = 0.f;

    // 512 float4 per row; 256 threads -> 2 iterations
    for (int i = t; i < D_DIM / 4; i += 256) {
        float4 xv = xr[i];
#pragma unroll
        for (int e = 0; e < E_NUM; e++) {
            float4 wv = reinterpret_cast<const float4*>(Wr + e * D_DIM)[i];
            acc[e] += xv.x * wv.x + xv.y * wv.y + xv.z * wv.z + xv.w * wv.w;
        }
    }

    __shared__ float sred[E_NUM][8];   // [expert][warp]
    const int lane = t & 31, warp = t >> 5;
#pragma unroll
    for (int e = 0; e < E_NUM; e++) {
        float v = acc[e];
#pragma unroll
        for (int off = 16; off > 0; off >>= 1)
            v += __shfl_down_sync(0xffffffffu, v, off);
        if (lane == 0) sred[e][warp] = v;
    }
    __syncthreads();

    if (t == 0) {
        float lg[E_NUM];
#pragma unroll
        for (int e = 0; e < E_NUM; e++) {
            float s = 0.f;
#pragma unroll
            for (int w = 0; w < 8; w++) s += sred[e][w];
            lg[e] = s;
        }
        // top-2 (first-index wins ties, matching jax top_k)
        int i1 = 0;
#pragma unroll
        for (int e = 1; e < E_NUM; e++) if (lg[e] > lg[i1]) i1 = e;
        int i2 = -1;
#pragma unroll
        for (int e = 0; e < E_NUM; e++) {
            if (e == i1) continue;
            if (i2 < 0 || lg[e] > lg[i2]) i2 = e;
        }
        float mx = lg[i1];
        float e1 = 1.0f;                 // exp(0)
        float e2 = __expf(lg[i2] - mx);
        float inv = 1.0f / (e1 + e2);
        float* dst = g_rw + (size_t)row * E_NUM;
#pragma unroll
        for (int e = 0; e < E_NUM; e++) dst[e] = 0.f;
        dst[i1] = e1 * inv;
        dst[i2] = e2 * inv;
    }
}

// ---------------------------------------------------------------------------
// Kernel 2: build WB[o][k]: k<2048 -> W[o][k];  k>=2048 -> Bexp[(k-2048)*O + o]
// (Bexp (E,R,O) flattened is exactly Bcat (128 x O) row-major.)
// One block per output row o.
// ---------------------------------------------------------------------------
__global__ __launch_bounds__(256) void build_wb_kernel(
    const float* __restrict__ W, const float* __restrict__ Bexp)
{
    const int o = blockIdx.x;
    const int t = threadIdx.x;
    const float4* src = reinterpret_cast<const float4*>(W + (size_t)o * D_DIM);
    float4* dst = reinterpret_cast<float4*>(g_WB + (size_t)o * K_TOT);
    for (int i = t; i < D_DIM / 4; i += 256) dst[i] = src[i];
    if (t < KLORA)
        g_WB[(size_t)o * K_TOT + D_DIM + t] = Bexp[(size_t)t * O_DIM + o];
}

// ---------------------------------------------------------------------------
// Kernel 3: Z = (X @ Acat) * rw_expanded.  M=8192, N=128, K=2048.
// Tile: 64(M) x 128(N, all) x 16(K), 256 threads, 4x8 microtile.
// B tile gathered directly from A (E,D,R): Acat[d][e*16+r] = A[e*D*R + d*R + r]
// ---------------------------------------------------------------------------
__global__ __launch_bounds__(256) void zgemm_kernel(
    const float* __restrict__ x, const float* __restrict__ A)
{
    __shared__ float As[16][68];    // [k][m], pad: 68*4=272B = 17*16, float4-aligned rows
    __shared__ float Bs[16][132];   // [k][n], 132*4=528B = 33*16

    const int m0 = blockIdx.x * 64;
    const int t = threadIdx.x;
    const int tm = t & 15;          // 16 m-threads * 4 = 64
    const int tn = t >> 4;          // 16 n-threads * 8 = 128

    float acc[4][8];
#pragma unroll
    for (int i = 0; i < 4; i++)
#pragma unroll
        for (int j = 0; j < 8; j++) acc[i][j] = 0.f;

    const int arow = t >> 2;            // 0..63
    const int ac4 = (t & 3) * 4;        // k offset 0,4,8,12
    const float* aptr = x + (size_t)(m0 + arow) * D_DIM + ac4;

    for (int k0 = 0; k0 < D_DIM; k0 += 16) {
        // A tile: 64x16, one float4 per thread, store transposed
        float4 av = *reinterpret_cast<const float4*>(aptr + k0);
        As[ac4 + 0][arow] = av.x;
        As[ac4 + 1][arow] = av.y;
        As[ac4 + 2][arow] = av.z;
        As[ac4 + 3][arow] = av.w;
        // B tile: 16x128 gathered from A tensor
#pragma unroll
        for (int i = 0; i < 8; i++) {
            int idx = t + i * 256;
            int kk = idx >> 7;          // 0..15
            int j = idx & 127;
            Bs[kk][j] = A[(size_t)(j >> 4) * (D_DIM * R_DIM)
                          + (size_t)(k0 + kk) * R_DIM + (j & 15)];
        }
        __syncthreads();

#pragma unroll
        for (int kk = 0; kk < 16; kk++) {
            float4 a0 = *reinterpret_cast<const float4*>(&As[kk][tm * 4]);
            float4 b0 = *reinterpret_cast<const float4*>(&Bs[kk][tn * 8]);
            float4 b1 = *reinterpret_cast<const float4*>(&Bs[kk][tn * 8 + 4]);
            float am[4] = {a0.x, a0.y, a0.z, a0.w};
            float bn[8] = {b0.x, b0.y, b0.z, b0.w, b1.x, b1.y, b1.z, b1.w};
#pragma unroll
            for (int i = 0; i < 4; i++)
#pragma unroll
                for (int j = 0; j < 8; j++)
                    acc[i][j] = fmaf(am[i], bn[j], acc[i][j]);
        }
        __syncthreads();
    }

    // epilogue: scale by router weight; expert index constant per thread
    const int e = tn >> 1;   // (tn*8 + j) >> 4 for j in [0,8)
#pragma unroll
    for (int i = 0; i < 4; i++) {
        int m = m0 + tm * 4 + i;
        float w = g_rw[(size_t)m * E_NUM + e];
        float4 v0 = {acc[i][0] * w, acc[i][1] * w, acc[i][2] * w, acc[i][3] * w};
        float4 v1 = {acc[i][4] * w, acc[i][5] * w, acc[i][6] * w, acc[i][7] * w};
        float* zp = g_Z + (size_t)m * KLORA + tn * 8;
        *reinterpret_cast<float4*>(zp) = v0;
        *reinterpret_cast<float4*>(zp + 4) = v1;
    }
}

// ---------------------------------------------------------------------------
// Kernel 4: out = [X|Z] @ WB^T + bias.  M=8192, N=2048, K=2176.
// Tile 128x128x16, 256 threads, 8x8 microtile. A-operand switches source
// (x -> g_Z) at k=2048 (tile-aligned).
// ---------------------------------------------------------------------------
__global__ __launch_bounds__(256) void mgemm_kernel(
    const float* __restrict__ x, const float* __restrict__ bias,
    float* __restrict__ out)
{
    __shared__ float As[16][132];
    __shared__ float Bs[16][132];

    const int n0 = blockIdx.x * 128;
    const int m0 = blockIdx.y * 128;
    const int t = threadIdx.x;
    const int tm = t & 15;
    const int tn = t >> 4;

    float acc[8][8];
#pragma unroll
    for (int i = 0; i < 8; i++)
#pragma unroll
        for (int j = 0; j < 8; j++) acc[i][j] = 0.f;

    // loads: 128x16 tile = 512 float4; thread does idx = t and t+256
    for (int k0 = 0; k0 < K_TOT; k0 += 16) {
        const float* abase;
        size_t astride;
        if (k0 < D_DIM) { abase = x + k0; astride = D_DIM; }
        else            { abase = g_Z + (k0 - D_DIM); astride = KLORA; }

#pragma unroll
        for (int i = 0; i < 2; i++) {
            int idx = t + i * 256;
            int row = idx >> 2;
            int c4 = (idx & 3) * 4;
            float4 v = *reinterpret_cast<const float4*>(
                abase + (size_t)(m0 + row) * astride + c4);
            As[c4 + 0][row] = v.x;
            As[c4 + 1][row] = v.y;
            As[c4 + 2][row] = v.z;
            As[c4 + 3][row] = v.w;
        }
#pragma unroll
        for (int i = 0; i < 2; i++) {
            int idx = t + i * 256;
            int row = idx >> 2;
            int c4 = (idx & 3) * 4;
            float4 v = *reinterpret_cast<const float4*>(
                g_WB + (size_t)(n0 + row) * K_TOT + k0 + c4);
            Bs[c4 + 0][row] = v.x;
            Bs[c4 + 1][row] = v.y;
            Bs[c4 + 2][row] = v.z;
            Bs[c4 + 3][row] = v.w;
        }
        __syncthreads();

#pragma unroll
        for (int kk = 0; kk < 16; kk++) {
            float4 a0 = *reinterpret_cast<const float4*>(&As[kk][tm * 8]);
            float4 a1 = *reinterpret_cast<const float4*>(&As[kk][tm * 8 + 4]);
            float4 b0 = *reinterpret_cast<const float4*>(&Bs[kk][tn * 8]);
            float4 b1 = *reinterpret_cast<const float4*>(&Bs[kk][tn * 8 + 4]);
            float am[8] = {a0.x, a0.y, a0.z, a0.w, a1.x, a1.y, a1.z, a1.w};
            float bn[8] = {b0.x, b0.y, b0.z, b0.w, b1.x, b1.y, b1.z, b1.w};
#pragma unroll
            for (int i = 0; i < 8; i++)
#pragma unroll
                for (int j = 0; j < 8; j++)
                    acc[i][j] = fmaf(am[i], bn[j], acc[i][j]);
        }
        __syncthreads();
    }

    float bj[8];
#pragma unroll
    for (int j = 0; j < 8; j++) bj[j] = bias[n0 + tn * 8 + j];

#pragma unroll
    for (int i = 0; i < 8; i++) {
        int m = m0 + tm * 8 + i;
        float4 v0 = {acc[i][0] + bj[0], acc[i][1] + bj[1],
                     acc[i][2] + bj[2], acc[i][3] + bj[3]};
        float4 v1 = {acc[i][4] + bj[4], acc[i][5] + bj[5],
                     acc[i][6] + bj[6], acc[i][7] + bj[7]};
        float* op = out + (size_t)m * O_DIM + n0 + tn * 8;
        *reinterpret_cast<float4*>(op) = v0;
        *reinterpret_cast<float4*>(op + 4) = v1;
    }
}

// ---------------------------------------------------------------------------
extern "C" void kernel_launch(void* const* d_in, const int* in_sizes, int n_in,
                              void* d_out, int out_size)
{
    const float* x    = (const float*)d_in[0];   // (4,2048,2048)
    const float* W    = (const float*)d_in[1];   // (2048,2048)
    const float* bias = (const float*)d_in[2];   // (2048,)
    const float* Wr   = (const float*)d_in[3];   // (8,2048)
    const float* A    = (const float*)d_in[4];   // (8,2048,16)
    const float* Bexp = (const float*)d_in[5];   // (8,16,2048)
    float* out = (float*)d_out;                  // (4,2048,2048)

    router_kernel<<<M_TOT, 256>>>(x, Wr);
    build_wb_kernel<<<O_DIM, 256>>>(W, Bexp);
    zgemm_kernel<<<M_TOT / 64, 256>>>(x, A);
    mgemm_kernel<<<dim3(O_DIM / 128, M_TOT / 128), 256>>>(x, bias, out);
}

// round 6
// speedup vs baseline: 2.4229x; 2.4229x over previous
#include <cuda_runtime.h>
#include <cuda_bf16.h>
#include <cstdint>

#define M_TOT 8192
#define D_DIM 2048
#define O_DIM 2048
#define E_NUM 8
#define R_DIM 16
#define KLORA 128
#define K_TOT 2176          // D_DIM + KLORA

// ---------------- scratch (bf16 stored as ushort) ----------------
__device__ float g_rw[M_TOT * E_NUM];
__device__ unsigned short g_Ahi[(size_t)M_TOT * K_TOT];   // [X|Z] hi, 35.7 MB
__device__ unsigned short g_Alo[(size_t)M_TOT * K_TOT];
__device__ unsigned short g_Bhi[(size_t)O_DIM * K_TOT];   // [W|Bcat] hi, 8.9 MB
__device__ unsigned short g_Blo[(size_t)O_DIM * K_TOT];
__device__ unsigned short g_Achi[(size_t)KLORA * D_DIM];  // Acat^T [128][2048]
__device__ unsigned short g_Aclo[(size_t)KLORA * D_DIM];

// ---------------- helpers ----------------
__device__ __forceinline__ uint32_t s2u(const void* p) {
    uint32_t a;
    asm("{ .reg .u64 t; cvta.to.shared.u64 t, %1; cvt.u32.u64 %0, t; }"
        : "=r"(a) : "l"(p));
    return a;
}
__device__ __forceinline__ void cp16(uint32_t dst, const void* src) {
    asm volatile("cp.async.cg.shared.global [%0], [%1], 16;" :: "r"(dst), "l"(src));
}
#define CP_COMMIT() asm volatile("cp.async.commit_group;" ::: "memory")
#define CP_WAIT1()  asm volatile("cp.async.wait_group 1;" ::: "memory")

__device__ __forceinline__ void ldm_x4(uint32_t* r, uint32_t addr) {
    asm volatile("ldmatrix.sync.aligned.m8n8.x4.shared.b16 {%0,%1,%2,%3}, [%4];"
        : "=r"(r[0]), "=r"(r[1]), "=r"(r[2]), "=r"(r[3]) : "r"(addr));
}
__device__ __forceinline__ void mma_bf16(float* d, const uint32_t* a,
                                         uint32_t b0, uint32_t b1) {
    asm volatile(
        "mma.sync.aligned.m16n8k16.row.col.f32.bf16.bf16.f32 "
        "{%0,%1,%2,%3}, {%4,%5,%6,%7}, {%8,%9}, {%0,%1,%2,%3};"
        : "+f"(d[0]), "+f"(d[1]), "+f"(d[2]), "+f"(d[3])
        : "r"(a[0]), "r"(a[1]), "r"(a[2]), "r"(a[3]), "r"(b0), "r"(b1));
}
__device__ __forceinline__ unsigned short bf_hi(float v) {
    return __bfloat16_as_ushort(__float2bfloat16_rn(v));
}
__device__ __forceinline__ unsigned short bf_lo(float v) {
    float h = __bfloat162float(__float2bfloat16_rn(v));
    return __bfloat16_as_ushort(__float2bfloat16_rn(v - h));
}

// ---------------------------------------------------------------------------
// Prep 1: x -> bf16 hi/lo splits into g_Ahi/g_Alo cols [0,2048);
// router logits + top-2 softmax -> g_rw. 32 rows per block, Wr cached in smem.
// ---------------------------------------------------------------------------
__global__ __launch_bounds__(256) void prep_rs_kernel(
    const float* __restrict__ x, const float* __restrict__ Wr)
{
    extern __shared__ float psm[];
    float* wr_s = psm;            // 16384 floats = 64KB
    float* sred = psm + 16384;    // 64 floats
    const int tid = threadIdx.x;
    const int lane = tid & 31, warp = tid >> 5;

    for (int i = tid; i < 4096; i += 256)
        reinterpret_cast<float4*>(wr_s)[i] = reinterpret_cast<const float4*>(Wr)[i];
    __syncthreads();

    const int m0 = blockIdx.x * 32;
    for (int r = 0; r < 32; r++) {
        const int m = m0 + r;
        const float4* xr = reinterpret_cast<const float4*>(x + (size_t)m * D_DIM);
        float acc[E_NUM];
#pragma unroll
        for (int e = 0; e < E_NUM; e++) acc[e] = 0.f;

#pragma unroll
        for (int it = 0; it < 2; it++) {
            int i = tid + it * 256;
            float4 xv = xr[i];
            ushort4 hv, lv;
            hv.x = bf_hi(xv.x); lv.x = bf_lo(xv.x);
            hv.y = bf_hi(xv.y); lv.y = bf_lo(xv.y);
            hv.z = bf_hi(xv.z); lv.z = bf_lo(xv.z);
            hv.w = bf_hi(xv.w); lv.w = bf_lo(xv.w);
            *reinterpret_cast<ushort4*>(g_Ahi + (size_t)m * K_TOT + i * 4) = hv;
            *reinterpret_cast<ushort4*>(g_Alo + (size_t)m * K_TOT + i * 4) = lv;
#pragma unroll
            for (int e = 0; e < E_NUM; e++) {
                float4 wv = reinterpret_cast<const float4*>(wr_s + e * D_DIM)[i];
                acc[e] += xv.x * wv.x + xv.y * wv.y + xv.z * wv.z + xv.w * wv.w;
            }
        }
#pragma unroll
        for (int e = 0; e < E_NUM; e++) {
            float v = acc[e];
#pragma unroll
            for (int off = 16; off > 0; off >>= 1)
                v += __shfl_down_sync(0xffffffffu, v, off);
            if (lane == 0) sred[e * 8 + warp] = v;
        }
        __syncthreads();
        if (tid == 0) {
            float lg[E_NUM];
#pragma unroll
            for (int e = 0; e < E_NUM; e++) {
                float s = 0.f;
#pragma unroll
                for (int w = 0; w < 8; w++) s += sred[e * 8 + w];
                lg[e] = s;
            }
            int i1 = 0;
#pragma unroll
            for (int e = 1; e < E_NUM; e++) if (lg[e] > lg[i1]) i1 = e;
            int i2 = -1;
#pragma unroll
            for (int e = 0; e < E_NUM; e++) {
                if (e == i1) continue;
                if (i2 < 0 || lg[e] > lg[i2]) i2 = e;
            }
            float e2 = __expf(lg[i2] - lg[i1]);
            float inv = 1.0f / (1.0f + e2);
            float* dst = g_rw + (size_t)m * E_NUM;
#pragma unroll
            for (int e = 0; e < E_NUM; e++) dst[e] = 0.f;
            dst[i1] = inv;
            dst[i2] = e2 * inv;
        }
        __syncthreads();
    }
}

// ---------------------------------------------------------------------------
// Prep 2: W -> g_Bhi/g_Blo cols [0,2048); Bexp -> cols [2048,2176).
// ---------------------------------------------------------------------------
__global__ __launch_bounds__(256) void split_wb_kernel(
    const float* __restrict__ W, const float* __restrict__ Bexp)
{
    const int o = blockIdx.x;
    const int tid = threadIdx.x;
    const float4* src = reinterpret_cast<const float4*>(W + (size_t)o * D_DIM);
    for (int i = tid; i < D_DIM / 4; i += 256) {
        float4 v = src[i];
        ushort4 hv, lv;
        hv.x = bf_hi(v.x); lv.x = bf_lo(v.x);
        hv.y = bf_hi(v.y); lv.y = bf_lo(v.y);
        hv.z = bf_hi(v.z); lv.z = bf_lo(v.z);
        hv.w = bf_hi(v.w); lv.w = bf_lo(v.w);
        *reinterpret_cast<ushort4*>(g_Bhi + (size_t)o * K_TOT + i * 4) = hv;
        *reinterpret_cast<ushort4*>(g_Blo + (size_t)o * K_TOT + i * 4) = lv;
    }
    if (tid < KLORA) {
        float v = Bexp[(size_t)tid * O_DIM + o];
        g_Bhi[(size_t)o * K_TOT + D_DIM + tid] = bf_hi(v);
        g_Blo[(size_t)o * K_TOT + D_DIM + tid] = bf_lo(v);
    }
}

// ---------------------------------------------------------------------------
// Prep 3: Acat^T splits: g_Achi[n][k], n = e*16+r.
// ---------------------------------------------------------------------------
__global__ __launch_bounds__(256) void split_acat_kernel(const float* __restrict__ A)
{
    const int n = blockIdx.x;
    const int e = n >> 4, r = n & 15;
    const int tid = threadIdx.x;
    for (int k = tid; k < D_DIM; k += 256) {
        float v = A[(size_t)e * D_DIM * R_DIM + (size_t)k * R_DIM + r];
        g_Achi[(size_t)n * D_DIM + k] = bf_hi(v);
        g_Aclo[(size_t)n * D_DIM + k] = bf_lo(v);
    }
}

// ---------------------------------------------------------------------------
// Shared GEMM machinery: 128x128 block tile, BK=64, 3 stages, 8 warps,
// warp tile 32(m) x 64(n), m16n8k16 bf16 mma. K split into 3 segments
// (hi*hi, lo*hi, hi*lo) of a bf16x3 fp32 emulation.
// smem per stage: A 16KB + B 16KB = 32KB; 3 stages = 96KB.
// ---------------------------------------------------------------------------
#define STG_BYTES 32768
#define GSMEM (3 * STG_BYTES)

// swizzled byte offset within a tile: row (0..127), 16B-chunk c (0..7)
__device__ __forceinline__ uint32_t tswz(int row, int cbyte) {
    return (uint32_t)(row * 128 + (cbyte ^ ((row & 7) << 4)));
}

#define GEMM_LOAD(Asrc, Astride, Bsrc, Bstride, s)                                \
    do {                                                                          \
        uint32_t Ab_ = sb + (s) * STG_BYTES, Bb_ = Ab_ + 16384;                   \
        _Pragma("unroll")                                                         \
        for (int j_ = 0; j_ < 4; j_++) {                                          \
            int idx_ = tid + j_ * 256;                                            \
            int row_ = idx_ >> 3, c_ = idx_ & 7;                                  \
            uint32_t off_ = tswz(row_, c_ * 16);                                  \
            cp16(Ab_ + off_, (Asrc) + (size_t)row_ * (Astride) + c_ * 8);         \
            cp16(Bb_ + off_, (Bsrc) + (size_t)row_ * (Bstride) + c_ * 8);         \
        }                                                                         \
    } while (0)

#define GEMM_COMPUTE(s)                                                           \
    do {                                                                          \
        uint32_t Ab_ = sb + (s) * STG_BYTES, Bb_ = Ab_ + 16384;                   \
        _Pragma("unroll")                                                         \
        for (int kb_ = 0; kb_ < 4; kb_++) {                                       \
            uint32_t a_[2][4], b_[4][4];                                          \
            int colb_ = kb_ * 32 + (lane >> 4) * 16;                              \
            _Pragma("unroll")                                                     \
            for (int mt_ = 0; mt_ < 2; mt_++) {                                   \
                int row_ = wm * 32 + mt_ * 16 + (lane & 15);                      \
                ldm_x4(a_[mt_], Ab_ + tswz(row_, colb_));                         \
            }                                                                     \
            _Pragma("unroll")                                                     \
            for (int nt_ = 0; nt_ < 4; nt_++) {                                   \
                int row_ = wn * 64 + nt_ * 16 + (lane & 15);                      \
                ldm_x4(b_[nt_], Bb_ + tswz(row_, colb_));                         \
            }                                                                     \
            _Pragma("unroll")                                                     \
            for (int mt_ = 0; mt_ < 2; mt_++)                                     \
                _Pragma("unroll")                                                 \
                for (int ns_ = 0; ns_ < 8; ns_++)                                 \
                    mma_bf16(acc[mt_][ns_], a_[mt_],                              \
                             b_[ns_ >> 1][ns_ & 1], b_[ns_ >> 1][2 + (ns_ & 1)]); \
        }                                                                         \
    } while (0)

// ---------------------------------------------------------------------------
// zgemm: Z = (X @ Acat) * rw -> bf16 splits into g_Ahi/g_Alo cols [2048,2176).
// M=8192, N=128 (one block tile), K=2048 per segment -> 96 tiles.
// ---------------------------------------------------------------------------
__global__ void __launch_bounds__(256, 1) zgemm_mma_kernel()
{
    extern __shared__ __align__(128) char smem[];
    const uint32_t sb = s2u(smem);
    const int tid = threadIdx.x;
    const int lane = tid & 31, warp = tid >> 5;
    const int wm = warp & 3, wn = warp >> 2;
    const int m0 = blockIdx.x * 128;

    float acc[2][8][4];
#pragma unroll
    for (int i = 0; i < 2; i++)
#pragma unroll
        for (int j = 0; j < 8; j++)
#pragma unroll
            for (int k = 0; k < 4; k++) acc[i][j][k] = 0.f;

    const int NT = 96, SEG = 32;
    auto asrc = [&](int t) -> const unsigned short* {
        int seg = t / SEG, kk = (t % SEG) * 64;
        return ((seg == 1) ? g_Alo : g_Ahi) + (size_t)m0 * K_TOT + kk;
    };
    auto bsrc = [&](int t) -> const unsigned short* {
        int seg = t / SEG, kk = (t % SEG) * 64;
        return ((seg == 2) ? g_Aclo : g_Achi) + kk;
    };

    GEMM_LOAD(asrc(0), K_TOT, bsrc(0), D_DIM, 0); CP_COMMIT();
    GEMM_LOAD(asrc(1), K_TOT, bsrc(1), D_DIM, 1); CP_COMMIT();

    for (int t = 0; t < NT; t++) {
        CP_WAIT1();
        __syncthreads();
        if (t + 2 < NT) GEMM_LOAD(asrc(t + 2), K_TOT, bsrc(t + 2), D_DIM, (t + 2) % 3);
        CP_COMMIT();
        GEMM_COMPUTE(t % 3);
    }

    // epilogue: scale by router weight, split to bf16, store into A cols [2048,2176)
#pragma unroll
    for (int mt = 0; mt < 2; mt++)
#pragma unroll
        for (int ns = 0; ns < 8; ns++) {
            int m = m0 + wm * 32 + mt * 16 + (lane >> 2);
            int n = wn * 64 + ns * 8 + (lane & 3) * 2;
            int e = n >> 4;
            float w0 = g_rw[(size_t)m * E_NUM + e];
            float w1 = g_rw[(size_t)(m + 8) * E_NUM + e];
            float v0 = acc[mt][ns][0] * w0, v1 = acc[mt][ns][1] * w0;
            float v2 = acc[mt][ns][2] * w1, v3 = acc[mt][ns][3] * w1;
            ushort2 h0 = {bf_hi(v0), bf_hi(v1)}, l0 = {bf_lo(v0), bf_lo(v1)};
            ushort2 h1 = {bf_hi(v2), bf_hi(v3)}, l1 = {bf_lo(v2), bf_lo(v3)};
            *reinterpret_cast<ushort2*>(g_Ahi + (size_t)m * K_TOT + D_DIM + n) = h0;
            *reinterpret_cast<ushort2*>(g_Alo + (size_t)m * K_TOT + D_DIM + n) = l0;
            *reinterpret_cast<ushort2*>(g_Ahi + (size_t)(m + 8) * K_TOT + D_DIM + n) = h1;
            *reinterpret_cast<ushort2*>(g_Alo + (size_t)(m + 8) * K_TOT + D_DIM + n) = l1;
        }
}

// ---------------------------------------------------------------------------
// mgemm: out = [X|Z] @ [W|Bcat]^T + bias.  K=2176 per segment -> 102 tiles.
// ---------------------------------------------------------------------------
__global__ void __launch_bounds__(256, 1) mgemm_mma_kernel(
    const float* __restrict__ bias, float* __restrict__ out)
{
    extern __shared__ __align__(128) char smem[];
    const uint32_t sb = s2u(smem);
    const int tid = threadIdx.x;
    const int lane = tid & 31, warp = tid >> 5;
    const int wm = warp & 3, wn = warp >> 2;
    const int n0 = blockIdx.x * 128;
    const int m0 = blockIdx.y * 128;

    float acc[2][8][4];
#pragma unroll
    for (int i = 0; i < 2; i++)
#pragma unroll
        for (int j = 0; j < 8; j++)
#pragma unroll
            for (int k = 0; k < 4; k++) acc[i][j][k] = 0.f;

    const int NT = 102, SEG = 34;
    auto asrc = [&](int t) -> const unsigned short* {
        int seg = t / SEG, kk = (t % SEG) * 64;
        return ((seg == 1) ? g_Alo : g_Ahi) + (size_t)m0 * K_TOT + kk;
    };
    auto bsrc = [&](int t) -> const unsigned short* {
        int seg = t / SEG, kk = (t % SEG) * 64;
        return ((seg == 2) ? g_Blo : g_Bhi) + (size_t)n0 * K_TOT + kk;
    };

    GEMM_LOAD(asrc(0), K_TOT, bsrc(0), K_TOT, 0); CP_COMMIT();
    GEMM_LOAD(asrc(1), K_TOT, bsrc(1), K_TOT, 1); CP_COMMIT();

    for (int t = 0; t < NT; t++) {
        CP_WAIT1();
        __syncthreads();
        if (t + 2 < NT) GEMM_LOAD(asrc(t + 2), K_TOT, bsrc(t + 2), K_TOT, (t + 2) % 3);
        CP_COMMIT();
        GEMM_COMPUTE(t % 3);
    }

    // epilogue: + bias, direct float2 stores
#pragma unroll
    for (int mt = 0; mt < 2; mt++)
#pragma unroll
        for (int ns = 0; ns < 8; ns++) {
            int m = m0 + wm * 32 + mt * 16 + (lane >> 2);
            int n = n0 + wn * 64 + ns * 8 + (lane & 3) * 2;
            float2 bv = *reinterpret_cast<const float2*>(bias + n);
            float2 v0 = {acc[mt][ns][0] + bv.x, acc[mt][ns][1] + bv.y};
            float2 v1 = {acc[mt][ns][2] + bv.x, acc[mt][ns][3] + bv.y};
            *reinterpret_cast<float2*>(out + (size_t)m * O_DIM + n) = v0;
            *reinterpret_cast<float2*>(out + (size_t)(m + 8) * O_DIM + n) = v1;
        }
}

// ---------------------------------------------------------------------------
extern "C" void kernel_launch(void* const* d_in, const int* in_sizes, int n_in,
                              void* d_out, int out_size)
{
    const float* x    = (const float*)d_in[0];
    const float* W    = (const float*)d_in[1];
    const float* bias = (const float*)d_in[2];
    const float* Wr   = (const float*)d_in[3];
    const float* A    = (const float*)d_in[4];
    const float* Bexp = (const float*)d_in[5];
    float* out = (float*)d_out;

    cudaFuncSetAttribute(prep_rs_kernel,
                         cudaFuncAttributeMaxDynamicSharedMemorySize, 66048);
    cudaFuncSetAttribute(zgemm_mma_kernel,
                         cudaFuncAttributeMaxDynamicSharedMemorySize, GSMEM);
    cudaFuncSetAttribute(mgemm_mma_kernel,
                         cudaFuncAttributeMaxDynamicSharedMemorySize, GSMEM);

    prep_rs_kernel<<<M_TOT / 32, 256, 66048>>>(x, Wr);
    split_wb_kernel<<<O_DIM, 256>>>(W, Bexp);
    split_acat_kernel<<<KLORA, 256>>>(A);
    zgemm_mma_kernel<<<M_TOT / 128, 256, GSMEM>>>();
    mgemm_mma_kernel<<<dim3(O_DIM / 128, M_TOT / 128), 256, GSMEM>>>(bias, out);
}